// round 1
// baseline (speedup 1.0000x reference)
#include <cuda_runtime.h>

#define RCH 64
#define GCH 128
#define ACH 80
#define SCH 64
#define TT 8192
#define BB 8
#define NPOS (BB*TT)      // 65536
#define NLAYERS 30
#define POSB 256          // positions per block
#define THR 512           // threads per block (2 threads per position)
#define KKC 192           // conv k-indices (3 taps * 64 ci)
#define KKT 272           // + 80 aux
#define SMEM_LAYER (KKT*64*8)   // 139264 bytes

__device__ float g_xa[BB*RCH*TT];
__device__ float g_xb[BB*RCH*TT];
__device__ float g_skip[BB*SCH*TT];

static __device__ __forceinline__ unsigned long long pk2(float lo, float hi) {
    unsigned long long r;
    asm("mov.b64 %0, {%1, %2};" : "=l"(r) : "f"(lo), "f"(hi));
    return r;
}
static __device__ __forceinline__ void upk2(unsigned long long v, float& lo, float& hi) {
    asm("mov.b64 {%0, %1}, %2;" : "=f"(lo), "=f"(hi) : "l"(v));
}
static __device__ __forceinline__ void fma2(unsigned long long& acc,
                                            unsigned long long w,
                                            unsigned long long x) {
    asm("fma.rn.f32x2 %0, %1, %2, %0;" : "+l"(acc) : "l"(w), "l"(x));
}

// ---------------------------------------------------------------------------
// first 1x1 conv (1 -> RC) + zero skip buffer
// ---------------------------------------------------------------------------
__global__ void k_first(const float* __restrict__ x,
                        const float* __restrict__ fw,
                        const float* __restrict__ fb) {
    int idx = blockIdx.x * blockDim.x + threadIdx.x;   // over RCH*NPOS
    int r = idx >> 16;          // channel
    int p = idx & (NPOS - 1);   // position
    int b = p >> 13;
    int t = p & (TT - 1);
    float v = fw[r] * x[p] + fb[r];
    g_xa[(b * RCH + r) * TT + t] = v;
    g_skip[(b * SCH + r) * TT + t] = 0.f;   // r in [0,64) == SCH
}

// ---------------------------------------------------------------------------
// fused WaveNet layer: dilated conv + aux 1x1 + gate + out 1x1 + residual/skip
// 2 threads per position; each computes 32 (lo,hi) channel pairs as f32x2.
// ---------------------------------------------------------------------------
__global__ void __launch_bounds__(THR, 1)
k_layer(int l, int d, int flip,
        const float* __restrict__ conv_w, const float* __restrict__ conv_b,
        const float* __restrict__ aux_w,  const float* __restrict__ out_w,
        const float* __restrict__ out_b,  const float* __restrict__ cond,
        const float* __restrict__ mask) {
    extern __shared__ char smraw[];
    float2* wsh = (float2*)smraw;

    const float* xin  = flip ? g_xb : g_xa;
    float*       xout = flip ? g_xa : g_xb;

    const int tid   = threadIdx.x;
    const int half  = tid >> 8;          // 0 or 1
    const int pidx  = tid & 255;
    const int p     = blockIdx.x * POSB + pidx;
    const int b     = p >> 13;
    const int t     = p & (TT - 1);
    const int cbase = half * 32;

    // ---- stage packed weights (h[c], h[c+64]) into smem -------------------
    const float* cw = conv_w + (size_t)l * GCH * RCH * 3;
    const float* aw = aux_w  + (size_t)l * GCH * ACH;
    for (int idx = tid; idx < KKT * 64; idx += THR) {
        int kk = idx >> 6, c = idx & 63;
        float lo, hi;
        if (kk < KKC) {
            int tap = kk >> 6, ci = kk & 63;
            lo = cw[(c * RCH + ci) * 3 + tap];
            hi = cw[((c + 64) * RCH + ci) * 3 + tap];
        } else {
            int j = kk - KKC;
            lo = aw[c * ACH + j];
            hi = aw[(c + 64) * ACH + j];
        }
        wsh[idx] = make_float2(lo, hi);
    }

    // ---- init accumulators with conv bias ----------------------------------
    unsigned long long acc[32];
    const float* cb = conv_b + l * GCH;
#pragma unroll
    for (int j = 0; j < 32; j++) acc[j] = pk2(cb[cbase + j], cb[64 + cbase + j]);

    __syncthreads();

    const unsigned long long* wsu = (const unsigned long long*)smraw;
    const float* xbp = xin + (size_t)b * RCH * TT + t;

    // ---- dilated conv taps --------------------------------------------------
#pragma unroll
    for (int tap = 0; tap < 3; ++tap) {
        const int off = (tap - 1) * d;
        const bool ok = (tap == 1) || (tap == 0 ? (t >= d) : (t + d < TT));
        const float* xq = xbp + off;
        for (int ci = 0; ci < RCH; ci += 4) {
            float xv[4];
#pragma unroll
            for (int u = 0; u < 4; u++) xv[u] = ok ? xq[(ci + u) * TT] : 0.f;
#pragma unroll
            for (int u = 0; u < 4; u++) {
                unsigned long long xx = pk2(xv[u], xv[u]);
                const unsigned long long* wrow =
                    wsu + ((tap * 64 + ci + u) * 64 + cbase);
#pragma unroll
                for (int jj = 0; jj < 32; jj += 2) {
                    longlong2 w = *(const longlong2*)(wrow + jj);
                    fma2(acc[jj],     (unsigned long long)w.x, xx);
                    fma2(acc[jj + 1], (unsigned long long)w.y, xx);
                }
            }
        }
    }

    // ---- aux (local conditioning) ------------------------------------------
    const float* cp = cond + (size_t)b * ACH * TT + t;
    for (int j0 = 0; j0 < ACH; j0 += 4) {
        float xv[4];
#pragma unroll
        for (int u = 0; u < 4; u++) xv[u] = cp[(j0 + u) * TT];
#pragma unroll
        for (int u = 0; u < 4; u++) {
            unsigned long long xx = pk2(xv[u], xv[u]);
            const unsigned long long* wrow =
                wsu + ((KKC + j0 + u) * 64 + cbase);
#pragma unroll
            for (int jj = 0; jj < 32; jj += 2) {
                longlong2 w = *(const longlong2*)(wrow + jj);
                fma2(acc[jj],     (unsigned long long)w.x, xx);
                fma2(acc[jj + 1], (unsigned long long)w.y, xx);
            }
        }
    }

    // ---- gated activation ---------------------------------------------------
    float z[32];
#pragma unroll
    for (int j = 0; j < 32; j++) {
        float a, g;
        upk2(acc[j], a, g);
        z[j] = tanhf(a) * (1.f / (1.f + expf(-g)));
    }

    __syncthreads();   // conv-weight reads done; smem is repurposed below

    float*  zsh = (float*)smraw;                 // [64][POSB] transposed
    float2* osh = (float2*)(smraw + 64 * POSB * 4);   // [64][64] pairs
#pragma unroll
    for (int j = 0; j < 32; j++) zsh[(cbase + j) * POSB + pidx] = z[j];

    const float* ow = out_w + (size_t)l * (RCH + SCH) * (GCH / 2);
    for (int idx = tid; idx < 64 * 64; idx += THR) {
        int j = idx >> 6, r = idx & 63;
        osh[j * 64 + r] = make_float2(ow[r * (GCH / 2) + j],
                                      ow[(64 + r) * (GCH / 2) + j]);
    }
    __syncthreads();

    // ---- out projection: pairs (o[r], o[r+64]) = (residual, skip) ----------
    unsigned long long oacc[32];
    const float* ob = out_b + l * (RCH + SCH);
#pragma unroll
    for (int j = 0; j < 32; j++) oacc[j] = pk2(ob[cbase + j], ob[64 + cbase + j]);

    const unsigned long long* osu = (const unsigned long long*)osh;
    for (int j = 0; j < GCH / 2; j += 2) {
#pragma unroll
        for (int u = 0; u < 2; u++) {
            float zv = zsh[(j + u) * POSB + pidx];
            unsigned long long zz = pk2(zv, zv);
            const unsigned long long* wr = osu + ((j + u) * 64 + cbase);
#pragma unroll
            for (int jj = 0; jj < 32; jj += 2) {
                longlong2 w = *(const longlong2*)(wr + jj);
                fma2(oacc[jj],     (unsigned long long)w.x, zz);
                fma2(oacc[jj + 1], (unsigned long long)w.y, zz);
            }
        }
    }

    // ---- mask, residual add, skip accumulate -------------------------------
    const float m = mask[p];
#pragma unroll
    for (int j = 0; j < 32; j++) {
        float res, sk;
        upk2(oacc[j], res, sk);
        int r = cbase + j;
        size_t xi = (size_t)(b * RCH + r) * TT + t;
        xout[xi] = xin[xi] + res * m;
        size_t si = (size_t)(b * SCH + r) * TT + t;
        g_skip[si] += sk * m;
    }
}

// ---------------------------------------------------------------------------
// last conv: ReLU -> 1x1(64->64) -> ReLU -> 1x1(64->1)
// ---------------------------------------------------------------------------
__global__ void k_last(const float* __restrict__ w1, const float* __restrict__ b1,
                       const float* __restrict__ w2, const float* __restrict__ b2,
                       float* __restrict__ out) {
    __shared__ float w1t[64 * 64];   // transposed [i][j]
    __shared__ float w2s[64];
    __shared__ float b1s[64];
    const int tid = threadIdx.x;
    for (int idx = tid; idx < 64 * 64; idx += 256) {
        int i = idx >> 6, j = idx & 63;
        w1t[i * 64 + j] = w1[j * 64 + i];
    }
    if (tid < 64) { w2s[tid] = w2[tid]; b1s[tid] = b1[tid]; }
    __syncthreads();

    const int p = blockIdx.x * 256 + tid;
    const int b = p >> 13;
    const int t = p & (TT - 1);

    float acc[64];
#pragma unroll
    for (int j = 0; j < 64; j++) acc[j] = b1s[j];

    const float* sp = g_skip + (size_t)b * SCH * TT + t;
    for (int i = 0; i < 64; i++) {
        float sv = fmaxf(sp[i * TT], 0.f);
#pragma unroll
        for (int j = 0; j < 64; j += 4) {
            float4 w = *(const float4*)(w1t + i * 64 + j);
            acc[j]     = fmaf(w.x, sv, acc[j]);
            acc[j + 1] = fmaf(w.y, sv, acc[j + 1]);
            acc[j + 2] = fmaf(w.z, sv, acc[j + 2]);
            acc[j + 3] = fmaf(w.w, sv, acc[j + 3]);
        }
    }
    float y = b2[0];
#pragma unroll
    for (int j = 0; j < 64; j++) y = fmaf(w2s[j], fmaxf(acc[j], 0.f), y);
    out[p] = y;
}

// ---------------------------------------------------------------------------
extern "C" void kernel_launch(void* const* d_in, const int* in_sizes, int n_in,
                              void* d_out, int out_size) {
    const float* x      = (const float*)d_in[0];
    const float* x_mask = (const float*)d_in[1];
    const float* c      = (const float*)d_in[2];
    const float* fw     = (const float*)d_in[3];
    const float* fb     = (const float*)d_in[4];
    const float* conv_w = (const float*)d_in[5];
    const float* conv_b = (const float*)d_in[6];
    const float* aux_w  = (const float*)d_in[7];
    const float* out_w  = (const float*)d_in[8];
    const float* out_b  = (const float*)d_in[9];
    const float* w1     = (const float*)d_in[10];
    const float* b1     = (const float*)d_in[11];
    const float* w2     = (const float*)d_in[12];
    const float* b2     = (const float*)d_in[13];

    cudaFuncSetAttribute(k_layer, cudaFuncAttributeMaxDynamicSharedMemorySize,
                         SMEM_LAYER);

    k_first<<<(RCH * NPOS) / THR, THR>>>(x, fw, fb);

    for (int l = 0; l < NLAYERS; l++) {
        int d = 1 << (l % 10);
        k_layer<<<NPOS / POSB, THR, SMEM_LAYER>>>(
            l, d, l & 1, conv_w, conv_b, aux_w, out_w, out_b, c, x_mask);
    }

    k_last<<<NPOS / 256, 256>>>(w1, b1, w2, b2, (float*)d_out);
}